// round 11
// baseline (speedup 1.0000x reference)
#include <cuda_runtime.h>
#include <cstdint>
#include <cstddef>

// Fixed shapes
#define Nn 4
#define Cc 32
#define SIN 262144                        // 64^3
#define SOUT 32768                        // 32^3
#define NPOINTS 131072
#define GI_ELEMS ((size_t)Nn * Cc * SIN)
#define GG_ELEMS (NPOINTS * 3)
#define NROWS (Nn * 64 * 64)              // 16384 row bins (n, z0, y0)
#define RCAP 64

#define TP_BLOCKS 4096                    // gout transpose tiles (1024 x 4n)
#define ZR_BLOCKS 1600                    // zero rowcnt + gGrid

// Static device scratch
__device__ float  g_gout_t[(size_t)NPOINTS * Cc];     // gOut channels-last [p][c] (16MB)
__device__ int    g_rowcnt[NROWS];
__device__ float4 g_recs[(size_t)NROWS * RCAP];       // {tx,ty,tz, bits(p | x0<<20)}

// ---------------- prep: gout transpose + zero rowcnt/gGrid ----------------
__global__ void __launch_bounds__(256) k_prep(const float* __restrict__ gOut,
                                              float* __restrict__ gGrid) {
    const int bx = blockIdx.x, t = threadIdx.x;
    if (bx < TP_BLOCKS) {
        __shared__ float tile[32][33];
        const int n = bx >> 10;
        const int s0 = (bx & 1023) * 32;
        {
            const int c = t >> 3, s4 = t & 7;
            const float4 v = __ldg((const float4*)(gOut + ((size_t)n * Cc + c) * SOUT + s0) + s4);
            tile[c][s4 * 4 + 0] = v.x; tile[c][s4 * 4 + 1] = v.y;
            tile[c][s4 * 4 + 2] = v.z; tile[c][s4 * 4 + 3] = v.w;
        }
        __syncthreads();
        {
            const int s = t >> 3, cq = t & 7;
            float4 w;
            w.x = tile[cq * 4 + 0][s]; w.y = tile[cq * 4 + 1][s];
            w.z = tile[cq * 4 + 2][s]; w.w = tile[cq * 4 + 3][s];
            ((float4*)(g_gout_t + ((size_t)n * SOUT + s0 + s) * Cc))[cq] = w;
        }
    } else {
        const int i = (bx - TP_BLOCKS) * 256 + t;
        if (i < NROWS) g_rowcnt[i] = 0;
        if (i < GG_ELEMS) gGrid[i] = 0.f;
    }
}

// ---------------- bin points by (n, z0, y0) row ----------------
__global__ void __launch_bounds__(256) k_bin(const float* __restrict__ grid) {
    const int p = blockIdx.x * 256 + threadIdx.x;
    const float gx = __ldg(grid + (size_t)p * 3 + 0);
    const float gy = __ldg(grid + (size_t)p * 3 + 1);
    const float gz = __ldg(grid + (size_t)p * 3 + 2);
    const float ix = (gx + 1.f) * 31.5f;
    const float iy = (gy + 1.f) * 31.5f;
    const float iz = (gz + 1.f) * 31.5f;
    const float fx = floorf(ix), fy = floorf(iy), fz = floorf(iz);
    const float tx = ix - fx, ty = iy - fy, tz = iz - fz;
    const int x0 = min(max((int)fx, 0), 63);
    const int y0 = min(max((int)fy, 0), 63);
    const int z0 = min(max((int)fz, 0), 63);
    const int n = p >> 15;
    const int bin = (n * 64 + z0) * 64 + y0;
    const int pos = atomicAdd(&g_rowcnt[bin], 1);
    if (pos < RCAP)
        g_recs[(size_t)bin * RCAP + pos] =
            make_float4(tx, ty, tz, __int_as_float(p | (x0 << 20)));
}

// ---------------- unified row kernel: grad_input + grad_grid ----------------
__global__ void __launch_bounds__(256) k_row(const float* __restrict__ inp,
                                             float* __restrict__ gInp,
                                             float* __restrict__ gGrid) {
    __shared__ float  s_inp[65][33];    // x=64 column is zero (boundary)
    __shared__ float  s_acc[65][33];    // x=64 column is a dummy sink
    __shared__ float4 s_recs[4][RCAP];
    __shared__ int    s_cnt[4];

    const int t = threadIdx.x;
    const int wid = t >> 5, lane = t & 31;
    const int n = blockIdx.x >> 12;
    const int z = (blockIdx.x >> 6) & 63;
    const int y = blockIdx.x & 63;
    const size_t rowoff = (size_t)z * 4096 + (size_t)y * 64;

    // Load input row: float4, spread to s_inp[x][c]
#pragma unroll
    for (int j = 0; j < 2; j++) {
        const int u = j * 256 + t;          // 0..511
        const int c = u >> 4, xq = u & 15;
        const float4 v = __ldcs((const float4*)(inp + ((size_t)(n * Cc + c)) * SIN + rowoff) + xq);
        s_inp[xq * 4 + 0][c] = v.x; s_inp[xq * 4 + 1][c] = v.y;
        s_inp[xq * 4 + 2][c] = v.z; s_inp[xq * 4 + 3][c] = v.w;
    }
    // Zero accumulators + boundary columns
#pragma unroll
    for (int j = 0; j < 8; j++) {
        const int idx = j * 256 + t;
        s_acc[idx & 63][idx >> 6] = 0.f;
    }
    if (t < 33) { s_inp[64][t] = 0.f; s_acc[64][t] = 0.f; }

    // Warps 0..3 load the 4 neighbor row-bins: wid = (dz<<1)|dy -> bin (z-dz, y-dy)
    if (wid < 4) {
        const int zp = z - (wid >> 1), yp = y - (wid & 1);
        int cnt = 0;
        if (zp >= 0 && yp >= 0) {
            const int bin = (n * 64 + zp) * 64 + yp;
            cnt = min(g_rowcnt[bin], RCAP);
            for (int e = lane; e < cnt; e += 32)
                s_recs[wid][e] = g_recs[(size_t)bin * RCAP + e];
        }
        if (lane == 0) s_cnt[wid] = cnt;
    }
    __syncthreads();

    // Flattened visit list: prefix offsets (uniform per thread)
    const int c0 = s_cnt[0], c1 = s_cnt[1], c2 = s_cnt[2], c3 = s_cnt[3];
    const int off1 = c0, off2 = c0 + c1, off3 = c0 + c1 + c2;
    const int total = off3 + c3;
    const bool lo16 = lane < 16;

    // Software-pipelined visit loop (one visit per warp per step, stride 8)
    int e = wid;
    float4 r; float go = 0.f; int b = 0;
    if (e < total) {
        b = (e >= off1) + (e >= off2) + (e >= off3);
        const int loc = e - ((b > 2) ? off3 : (b > 1) ? off2 : (b > 0) ? off1 : 0);
        r = s_recs[b][loc];
        const int p0 = __float_as_int(r.w) & 0xFFFFF;
        go = g_gout_t[(size_t)p0 * 32 + lane];
    }
    while (e < total) {
        const int en = e + 8;
        float4 rn; float gon = 0.f; int bn = 0;
        if (en < total) {
            bn = (en >= off1) + (en >= off2) + (en >= off3);
            const int loc = en - ((bn > 2) ? off3 : (bn > 1) ? off2 : (bn > 0) ? off1 : 0);
            rn = s_recs[bn][loc];
            const int pn = __float_as_int(rn.w) & 0xFFFFF;
            gon = g_gout_t[(size_t)pn * 32 + lane];
        }

        // ---- process (b, r, go) ----
        const int bits = __float_as_int(r.w);
        const int p = bits & 0xFFFFF;
        const int x0 = bits >> 20;
        const float wz = (b & 2) ? r.z : 1.f - r.z;
        const float wy = (b & 1) ? r.y : 1.f - r.y;
        const float wyz = wy * wz;
        const float wxa = 1.f - r.x, wxb = r.x;

        atomicAdd(&s_acc[x0][lane], wxa * wyz * go);
        atomicAdd(&s_acc[x0 + 1][lane], wxb * wyz * go);
        float Pa = go * s_inp[x0][lane];
        float Pb = go * s_inp[x0 + 1][lane];

        // Merged dual reduction: 6 shuffles (Pa -> lanes 0-15, Pb -> lanes 16-31)
        const float send = lo16 ? Pb : Pa;
        const float recv = __shfl_xor_sync(0xFFFFFFFFu, send, 16);
        float R = lo16 ? (Pa + recv) : (Pb + recv);
#pragma unroll
        for (int o = 8; o > 0; o >>= 1)
            R += __shfl_xor_sync(0xFFFFFFFFu, R, o);
        const float other = __shfl_xor_sync(0xFFFFFFFFu, R, 16);
        if (lane < 3) {
            const float PA = R, PB = other;    // lane<3 => lo16
            const float sy = (b & 1) ? 1.f : -1.f;
            const float sz = (b & 2) ? 1.f : -1.f;
            const float Q = wxa * PA + wxb * PB;
            const float vx = wyz * (PB - PA) * 31.5f;
            const float vy = sy * wz * Q * 31.5f;
            const float vz = sz * wy * Q * 31.5f;
            const float val = (lane == 0) ? vx : (lane == 1) ? vy : vz;
            atomicAdd(gGrid + (size_t)p * 3 + lane, val);
        }

        e = en; r = rn; go = gon; b = bn;
    }
    __syncthreads();

    // Write grad_input row: float4
#pragma unroll
    for (int j = 0; j < 2; j++) {
        const int u = j * 256 + t;
        const int c = u >> 4, xq = u & 15;
        float4 w;
        w.x = s_acc[xq * 4 + 0][c]; w.y = s_acc[xq * 4 + 1][c];
        w.z = s_acc[xq * 4 + 2][c]; w.w = s_acc[xq * 4 + 3][c];
        __stcs((float4*)(gInp + ((size_t)(n * Cc + c)) * SIN + rowoff) + xq, w);
    }
}

extern "C" void kernel_launch(void* const* d_in, const int* in_sizes, int n_in,
                              void* d_out, int out_size) {
    const float* gOut = (const float*)d_in[0];  // [N,C,Do,Ho,Wo]
    const float* inp  = (const float*)d_in[1];  // [N,C,D,H,W]
    const float* grid = (const float*)d_in[2];  // [N,Do,Ho,Wo,3]
    float* out = (float*)d_out;

    float* gInp  = out;              // [N,C,D,H,W]
    float* gGrid = out + GI_ELEMS;   // [N,Do,Ho,Wo,3]

    // 1) prep: gout transpose + zero rowcnt/gGrid
    k_prep<<<TP_BLOCKS + ZR_BLOCKS, 256>>>(gOut, gGrid);
    // 2) bin points by cell row
    k_bin<<<NPOINTS / 256, 256>>>(grid);
    // 3) unified row kernel
    k_row<<<NROWS, 256>>>(inp, gInp, gGrid);
}